// round 1
// baseline (speedup 1.0000x reference)
#include <cuda_runtime.h>
#include <cstdint>

#define NB 8
#define NPTS 32768
#define NC 128
#define NK 1024
#define CLUSTER 8
#define PTS_PER_CTA (NPTS / CLUSTER)     // 4096
#define NTHREADS 1024
#define PTS_PER_THREAD (PTS_PER_CTA / NTHREADS)  // 4

// sampled indices scratch (device global: no allocation allowed)
__device__ int g_idx[NB * NK];

struct SmemLayout {
    float4   coords[PTS_PER_CTA];   // 65536 B — for winner coord lookup only
    float    warp_v[32];
    int      warp_i[32];
    uint32_t cand[2][CLUSTER][8];   // double-buffered candidate slots, 32B each
    float4   winner;                // x, y, z, (idx bits)
};

__device__ __forceinline__ uint32_t smem_u32(const void* p) {
    uint32_t a;
    asm("{ .reg .u64 t; cvta.to.shared.u64 t, %1; cvt.u32.u64 %0, t; }"
        : "=r"(a) : "l"(p));
    return a;
}

__device__ __forceinline__ uint32_t mapa_rank(uint32_t laddr, uint32_t rank) {
    uint32_t r;
    asm("mapa.shared::cluster.u32 %0, %1, %2;" : "=r"(r) : "r"(laddr), "r"(rank));
    return r;
}

__device__ __forceinline__ void cluster_barrier() {
    asm volatile("barrier.cluster.arrive.aligned;" ::: "memory");
    asm volatile("barrier.cluster.wait.aligned;" ::: "memory");
}

__global__ void __launch_bounds__(NTHREADS, 1) __cluster_dims__(CLUSTER, 1, 1)
fps_kernel(const float* __restrict__ xyz)
{
    extern __shared__ char smem_raw[];
    SmemLayout* sm = reinterpret_cast<SmemLayout*>(smem_raw);

    const int t    = threadIdx.x;
    const int rank = blockIdx.x & (CLUSTER - 1);
    const int b    = blockIdx.x >> 3;
    const float* xb = xyz + (size_t)b * 3 * NPTS;

    const int g0 = rank * PTS_PER_CTA + t;   // global point index of this thread's first point

    float px[PTS_PER_THREAD], py[PTS_PER_THREAD], pz[PTS_PER_THREAD], dist[PTS_PER_THREAD];
    const float INF = __int_as_float(0x7f800000);
    const float NEG_INF = __int_as_float(0xff800000);

#pragma unroll
    for (int i = 0; i < PTS_PER_THREAD; i++) {
        int g = g0 + i * NTHREADS;
        px[i] = xb[g];
        py[i] = xb[NPTS + g];
        pz[i] = xb[2 * NPTS + g];
        sm->coords[t + i * NTHREADS] = make_float4(px[i], py[i], pz[i], 0.0f);
        dist[i] = INF;
    }
    // initial winner = point 0
    float wx = xb[0], wy = xb[NPTS], wz = xb[2 * NPTS];
    if (rank == 0 && t == 0) g_idx[b * NK] = 0;

    const int wid = t >> 5, lane = t & 31;
    uint32_t cand_base[2];
    cand_base[0] = smem_u32(&sm->cand[0][rank][0]);
    cand_base[1] = smem_u32(&sm->cand[1][rank][0]);

    __syncthreads();
    cluster_barrier();

    int p = 0;
    for (int k = 1; k < NK; k++) {
        // ---- distance update + local argmax (pure register math) ----
        float bestv = NEG_INF;
        int   besti = 0;
#pragma unroll
        for (int i = 0; i < PTS_PER_THREAD; i++) {
            float dx = px[i] - wx, dy = py[i] - wy, dz = pz[i] - wz;
            float d  = fmaf(dz, dz, fmaf(dy, dy, dx * dx));
            float nd = fminf(dist[i], d);
            dist[i] = nd;
            if (nd > bestv) { bestv = nd; besti = g0 + i * NTHREADS; }
        }
        // ---- warp reduce (first-index tiebreak) ----
#pragma unroll
        for (int o = 16; o > 0; o >>= 1) {
            float ov = __shfl_down_sync(0xffffffffu, bestv, o);
            int   oi = __shfl_down_sync(0xffffffffu, besti, o);
            if (ov > bestv || (ov == bestv && oi < besti)) { bestv = ov; besti = oi; }
        }
        if (lane == 0) { sm->warp_v[wid] = bestv; sm->warp_i[wid] = besti; }
        __syncthreads();

        // ---- block reduce (warp 0) + candidate broadcast to all cluster CTAs ----
        if (wid == 0) {
            bestv = sm->warp_v[lane];
            besti = sm->warp_i[lane];
#pragma unroll
            for (int o = 16; o > 0; o >>= 1) {
                float ov = __shfl_down_sync(0xffffffffu, bestv, o);
                int   oi = __shfl_down_sync(0xffffffffu, besti, o);
                if (ov > bestv || (ov == bestv && oi < besti)) { bestv = ov; besti = oi; }
            }
            if (lane == 0) {
                float4 c = sm->coords[besti - rank * PTS_PER_CTA];
                uint32_t laddr = cand_base[p];
                uint32_t vb = __float_as_uint(bestv);
                uint32_t xb_ = __float_as_uint(c.x);
                uint32_t yb = __float_as_uint(c.y);
                uint32_t zb = __float_as_uint(c.z);
#pragma unroll
                for (int r = 0; r < CLUSTER; r++) {
                    uint32_t ra = mapa_rank(laddr, (uint32_t)r);
                    asm volatile("st.shared::cluster.v4.b32 [%0], {%1,%2,%3,%4};"
                                 :: "r"(ra), "r"(vb), "r"((uint32_t)besti), "r"(xb_), "r"(yb)
                                 : "memory");
                    asm volatile("st.shared::cluster.b32 [%0], %1;"
                                 :: "r"(ra + 16), "r"(zb) : "memory");
                }
            }
        }
        cluster_barrier();   // release DSMEM candidate stores, acquire peers'

        // ---- cross-CTA winner (thread 0), broadcast via smem ----
        if (t == 0) {
            float bv = NEG_INF; int bi = 0;
            float bx = 0.f, by = 0.f, bz = 0.f;
#pragma unroll
            for (int r = 0; r < CLUSTER; r++) {
                const uint32_t* s = &sm->cand[p][r][0];
                float v = __uint_as_float(s[0]);
                int   i2 = (int)s[1];
                if (v > bv || (v == bv && i2 < bi)) {
                    bv = v; bi = i2;
                    bx = __uint_as_float(s[2]);
                    by = __uint_as_float(s[3]);
                    bz = __uint_as_float(s[4]);
                }
            }
            sm->winner = make_float4(bx, by, bz, __int_as_float(bi));
            if (rank == 0) g_idx[b * NK + k] = bi;
        }
        __syncthreads();
        float4 w = sm->winner;
        wx = w.x; wy = w.y; wz = w.z;
        p ^= 1;
    }
}

// out = [node_static (8,3,1024) | node_feature (8,128,1024)]
__global__ void __launch_bounds__(NK) gather_kernel(
    const float* __restrict__ xyz,
    const float* __restrict__ feat,
    float* __restrict__ out)
{
    int k = threadIdx.x;
    int c = blockIdx.x;     // 0..130: 0-2 -> xyz planes, 3..130 -> feature planes
    int b = blockIdx.y;
    int idx = g_idx[b * NK + k];
    if (c < 3) {
        out[(size_t)b * 3 * NK + (size_t)c * NK + k] =
            xyz[(size_t)b * 3 * NPTS + (size_t)c * NPTS + idx];
    } else {
        int cf = c - 3;
        out[(size_t)NB * 3 * NK + (size_t)b * NC * NK + (size_t)cf * NK + k] =
            feat[(size_t)b * NC * NPTS + (size_t)cf * NPTS + idx];
    }
}

extern "C" void kernel_launch(void* const* d_in, const int* in_sizes, int n_in,
                              void* d_out, int out_size)
{
    const float* xyz  = (const float*)d_in[0];
    const float* feat = (const float*)d_in[1];
    float* out = (float*)d_out;

    size_t smem = sizeof(SmemLayout);
    cudaFuncSetAttribute(fps_kernel, cudaFuncAttributeMaxDynamicSharedMemorySize, (int)smem);

    fps_kernel<<<NB * CLUSTER, NTHREADS, smem>>>(xyz);
    gather_kernel<<<dim3(NC + 3, NB), NK>>>(xyz, feat, out);
}